// round 3
// baseline (speedup 1.0000x reference)
#include <cuda_runtime.h>
#include <cstdint>

// Problem constants
#define N0 100000
#define N1 50000
#define N2 25000
#define N3 12500
#define E0 800000
#define E1 400000
#define E2 200000
#define D  256

// ---------------- scratch (device globals; no allocation allowed) ----------
__device__ float g_sum[N1 * D];
__device__ float g_cnt[N1];
__device__ float g_h1[N1 * D];
__device__ float g_h2[N2 * D];
__device__ int   g_is64;

// ---------------- dtype detection ------------------------------------------
__global__ void detect_kernel(const int* __restrict__ e) {
    if (blockIdx.x == 0 && threadIdx.x == 0) {
        int is64 = 1;
        for (int i = 1; i < 64; i += 2)
            if (e[i] != 0) is64 = 0;
        g_is64 = is64;
    }
}

// ---------------- zero scratch (vectorized) ----------------------------------
__global__ void zero_kernel(float4* __restrict__ sum, float* __restrict__ cnt, int M) {
    int n4 = M * (D / 4);
    int stride = gridDim.x * blockDim.x;
    float4 z = make_float4(0.f, 0.f, 0.f, 0.f);
    for (int i = blockIdx.x * blockDim.x + threadIdx.x; i < n4; i += stride)
        sum[i] = z;
    for (int i = blockIdx.x * blockDim.x + threadIdx.x; i < M; i += stride)
        cnt[i] = 0.0f;
}

// ---------------- edge scatter: one warp per edge, v4 reductions ------------
__device__ __forceinline__ void red_add_v4(float* p, float4 v) {
    asm volatile("red.global.add.v4.f32 [%0], {%1,%2,%3,%4};"
                 :: "l"(p), "f"(v.x), "f"(v.y), "f"(v.z), "f"(v.w)
                 : "memory");
}

__global__ void scatter_kernel(const float* __restrict__ h,
                               const void* __restrict__ eraw,
                               int E,
                               float* __restrict__ sum,
                               float* __restrict__ cnt) {
    int gw   = (blockIdx.x * blockDim.x + threadIdx.x) >> 5;
    int lane = threadIdx.x & 31;
    if (gw >= E) return;

    long long s, d;
    if (g_is64) {
        const long long* e = (const long long*)eraw;
        s = e[gw];
        d = e[(long long)E + gw];
    } else {
        const int* e = (const int*)eraw;
        s = e[gw];
        d = e[E + gw];
    }

    const float4* hrow = (const float4*)(h + s * D);
    float* srow = sum + d * D;

#pragma unroll
    for (int i = 0; i < 2; i++) {
        int idx = lane + 32 * i;
        float4 v = hrow[idx];
        red_add_v4(srow + idx * 4, v);
    }
    if (lane == 0) atomicAdd(cnt + d, 1.0f);
}

// ---------------- fused SAGE GEMM (TF32, fragment-ordered smem) --------------
// C[m,:] = (sum[m]/max(cnt[m],1)) @ Wl + h_dst[m] @ Wr + b   (optional ReLU)
// Block 128x128, 8 warps (4x2), warp tile 32x64, BK=16, double-buffered smem.
// Smem tiles are stored in mma-fragment order so the mainloop uses only LDS.128.

__device__ __forceinline__ unsigned f2tf(float f) {
    unsigned u;
    asm("cvt.rna.tf32.f32 %0, %1;" : "=r"(u) : "f"(f));
    return u;
}

__device__ __forceinline__ void mma_tf32(float c[4], const uint4& a,
                                         unsigned b0, unsigned b1) {
    asm volatile(
        "mma.sync.aligned.m16n8k8.row.col.f32.tf32.tf32.f32 "
        "{%0,%1,%2,%3}, {%4,%5,%6,%7}, {%8,%9}, {%0,%1,%2,%3};"
        : "+f"(c[0]), "+f"(c[1]), "+f"(c[2]), "+f"(c[3])
        : "r"(a.x), "r"(a.y), "r"(a.z), "r"(a.w), "r"(b0), "r"(b1));
}

// A fragment chunks: [mblk(0..7)][ks(0..1)] -> 128 floats (lane*4 + reg)
// B fragment chunks: [ks(0..1)][pair(0..7)] -> 128 floats (lane*4 + (nblk&1)*2 + reg)
#define CHUNK 128
#define BUFSZ 2048   // 16 chunks

__global__ void __launch_bounds__(256, 2)
sage_gemm_tc(const float* __restrict__ A1,
             const float* __restrict__ A2,
             const float* __restrict__ cnt,
             const float* __restrict__ Wl,
             const float* __restrict__ Wr,
             const float* __restrict__ bias,
             float* __restrict__ C,
             int M, int do_relu) {
    __shared__ float As[2 * BUFSZ];
    __shared__ float Bs[2 * BUFSZ];

    const int tid  = threadIdx.x;
    const int lane = tid & 31;
    const int warp = tid >> 5;
    const int wm   = warp >> 1;
    const int wn   = warp & 1;
    const int row0 = blockIdx.y * 128;
    const int col0 = blockIdx.x * 128;

    // A staging mapping: thread -> (row 0..127, 8 cols at ks = tid&1)
    const int arow   = tid >> 1;
    const int aks    = tid & 1;
    const int garow  = row0 + arow;
    const int amblk  = arow >> 4;
    const int arr    = arow & 15;
    // base index of this thread's A chunk
    const int abase  = ((amblk * 2 + aks) << 7);
    const int alane0 = (arr & 7) << 2;          // lane component from row
    const int arbit  = (arr >> 3) & 1;          // reg bit from row

    // B staging mapping: thread -> (k-row 0..15, 8 cols)
    const int bk     = tid >> 4;
    const int bks    = bk >> 3;
    const int bkk    = bk & 7;
    const int btig   = bkk & 3;
    const int brbit  = bkk >> 2;
    const int bnblk  = tid & 15;
    const int bpair  = bnblk >> 1;
    const int boff   = ((bnblk & 1) << 1) + brbit;
    const int bbase  = ((bks * 8 + bpair) << 7);

    float rcp = 1.0f;
    if (garow < M) rcp = 1.0f / fmaxf(cnt[garow], 1.0f);

    float acc[2][8][4];
#pragma unroll
    for (int mi = 0; mi < 2; mi++)
#pragma unroll
        for (int ni = 0; ni < 8; ni++)
#pragma unroll
            for (int j = 0; j < 4; j++) acc[mi][ni][j] = 0.0f;

    // it in [0,32): phase = it>>4, k0 = (it&15)*16, buf = it&1
#define STAGE(it)                                                              \
    {                                                                          \
        const int phase_ = (it) >> 4;                                          \
        const int k0_    = ((it) & 15) << 4;                                   \
        float* as_ = &As[((it) & 1) * BUFSZ];                                  \
        float* bs_ = &Bs[((it) & 1) * BUFSZ];                                  \
        const float* Ap = phase_ ? A2 : A1;                                    \
        const float* Bp = phase_ ? Wr : Wl;                                    \
        const float sc = phase_ ? 1.0f : rcp;                                  \
        float4 v0 = make_float4(0.f, 0.f, 0.f, 0.f), v1 = v0;                  \
        if (garow < M) {                                                       \
            const float* ap = Ap + (size_t)garow * D + k0_ + aks * 8;          \
            v0 = *(const float4*)ap;                                           \
            v1 = *(const float4*)(ap + 4);                                     \
        }                                                                      \
        float av[8] = {v0.x, v0.y, v0.z, v0.w, v1.x, v1.y, v1.z, v1.w};        \
        _Pragma("unroll")                                                      \
        for (int j = 0; j < 8; j++) {                                          \
            int lane_ = alane0 | (j & 3);                                      \
            int r_    = arbit | ((j >> 2) << 1);                               \
            as_[abase + (lane_ << 2) + r_] =                                   \
                __uint_as_float(f2tf(av[j] * sc));                             \
        }                                                                      \
        const float* bp = Bp + (size_t)(k0_ + bk) * D + col0 + bnblk * 8;      \
        float4 w0 = *(const float4*)bp;                                        \
        float4 w1 = *(const float4*)(bp + 4);                                  \
        float bv[8] = {w0.x, w0.y, w0.z, w0.w, w1.x, w1.y, w1.z, w1.w};        \
        _Pragma("unroll")                                                      \
        for (int j = 0; j < 8; j++) {                                          \
            int lane_ = (j << 2) | btig;                                       \
            bs_[bbase + (lane_ << 2) + boff] = __uint_as_float(f2tf(bv[j]));   \
        }                                                                      \
    }

    STAGE(0);

    for (int it = 0; it < 32; it++) {
        __syncthreads();
        if (it + 1 < 32) STAGE(it + 1);

        const float* as_ = &As[(it & 1) * BUFSZ];
        const float* bs_ = &Bs[(it & 1) * BUFSZ];
#pragma unroll
        for (int ks = 0; ks < 2; ks++) {
            uint4 a[2];
#pragma unroll
            for (int mi = 0; mi < 2; mi++)
                a[mi] = *(const uint4*)&as_[(((wm * 2 + mi) * 2 + ks) << 7) + (lane << 2)];
#pragma unroll
            for (int np = 0; np < 4; np++) {
                uint4 b = *(const uint4*)&bs_[((ks * 8 + wn * 4 + np) << 7) + (lane << 2)];
                mma_tf32(acc[0][np * 2],     a[0], b.x, b.y);
                mma_tf32(acc[1][np * 2],     a[1], b.x, b.y);
                mma_tf32(acc[0][np * 2 + 1], a[0], b.z, b.w);
                mma_tf32(acc[1][np * 2 + 1], a[1], b.z, b.w);
            }
        }
    }

    // epilogue
    const int lr = lane >> 2;
    const int lc = lane & 3;
#pragma unroll
    for (int mi = 0; mi < 2; mi++) {
        const int r = row0 + wm * 32 + mi * 16 + lr;
#pragma unroll
        for (int ni = 0; ni < 8; ni++) {
            const int cidx = col0 + wn * 64 + ni * 8 + lc * 2;
            const float bb0 = bias[cidx];
            const float bb1 = bias[cidx + 1];
            float v0 = acc[mi][ni][0] + bb0;
            float v1 = acc[mi][ni][1] + bb1;
            float v2 = acc[mi][ni][2] + bb0;
            float v3 = acc[mi][ni][3] + bb1;
            if (do_relu) {
                v0 = fmaxf(v0, 0.f); v1 = fmaxf(v1, 0.f);
                v2 = fmaxf(v2, 0.f); v3 = fmaxf(v3, 0.f);
            }
            if (r < M) {
                C[(size_t)r * D + cidx]     = v0;
                C[(size_t)r * D + cidx + 1] = v1;
            }
            if (r + 8 < M) {
                C[(size_t)(r + 8) * D + cidx]     = v2;
                C[(size_t)(r + 8) * D + cidx + 1] = v3;
            }
        }
    }
}

// ---------------- launch -----------------------------------------------------
extern "C" void kernel_launch(void* const* d_in, const int* in_sizes, int n_in,
                              void* d_out, int out_size) {
    const float* x   = (const float*)d_in[0];
    const void*  e0  = d_in[1];
    const void*  e1  = d_in[2];
    const void*  e2  = d_in[3];
    const float* Wl0 = (const float*)d_in[4];
    const float* b0  = (const float*)d_in[5];
    const float* Wr0 = (const float*)d_in[6];
    const float* Wl1 = (const float*)d_in[7];
    const float* b1  = (const float*)d_in[8];
    const float* Wr1 = (const float*)d_in[9];
    const float* Wl2 = (const float*)d_in[10];
    const float* b2  = (const float*)d_in[11];
    const float* Wr2 = (const float*)d_in[12];
    float* out = (float*)d_out;

    float *sum, *cnt, *h1, *h2;
    cudaGetSymbolAddress((void**)&sum, g_sum);
    cudaGetSymbolAddress((void**)&cnt, g_cnt);
    cudaGetSymbolAddress((void**)&h1,  g_h1);
    cudaGetSymbolAddress((void**)&h2,  g_h2);

    detect_kernel<<<1, 32>>>((const int*)e0);

    // ---- layer 0
    zero_kernel<<<592, 256>>>((float4*)sum, cnt, N1);
    scatter_kernel<<<(E0 + 7) / 8, 256>>>(x, e0, E0, sum, cnt);
    sage_gemm_tc<<<dim3(2, (N1 + 127) / 128), 256>>>(
        sum, x, cnt, Wl0, Wr0, b0, h1, N1, 1);

    // ---- layer 1
    zero_kernel<<<592, 256>>>((float4*)sum, cnt, N2);
    scatter_kernel<<<(E1 + 7) / 8, 256>>>(h1, e1, E1, sum, cnt);
    sage_gemm_tc<<<dim3(2, (N2 + 127) / 128), 256>>>(
        sum, h1, cnt, Wl1, Wr1, b1, h2, N2, 1);

    // ---- layer 2 (no ReLU)
    zero_kernel<<<592, 256>>>((float4*)sum, cnt, N3);
    scatter_kernel<<<(E2 + 7) / 8, 256>>>(h2, e2, E2, sum, cnt);
    sage_gemm_tc<<<dim3(2, (N3 + 127) / 128), 256>>>(
        sum, h2, cnt, Wl2, Wr2, b2, out, N3, 0);
}

// round 4
// speedup vs baseline: 1.5730x; 1.5730x over previous
#include <cuda_runtime.h>
#include <cstdint>

// Problem constants
#define N0 100000
#define N1 50000
#define N2 25000
#define N3 12500
#define E0 800000
#define E1 400000
#define E2 200000
#define D  256
#define MAXDEG 64
#define OVF_CAP 65536

// ---------------- scratch (device globals; no allocation allowed) ----------
__device__ float g_mean[N1 * D];       // per-layer mean buffer
__device__ float g_h1[N1 * D];
__device__ float g_h2[N2 * D];
__device__ int   g_bcnt[N1];           // per-dst degree
__device__ int   g_bins[N1 * MAXDEG];  // per-dst src lists
__device__ int2  g_ovf[OVF_CAP];       // overflow edges (never expected)
__device__ int   g_ovf_n;
__device__ int   g_is64;

// ---------------- dtype detection ------------------------------------------
__global__ void detect_kernel(const int* __restrict__ e) {
    if (blockIdx.x == 0 && threadIdx.x == 0) {
        int is64 = 1;
        for (int i = 1; i < 64; i += 2)
            if (e[i] != 0) is64 = 0;
        g_is64 = is64;
    }
}

// ---------------- zero degree counters ---------------------------------------
__global__ void zcnt_kernel(int* __restrict__ bcnt, int M) {
    int i = blockIdx.x * blockDim.x + threadIdx.x;
    if (i == 0) g_ovf_n = 0;
    if (i < M) bcnt[i] = 0;
}

// ---------------- edge binning ------------------------------------------------
__global__ void bin_kernel(const void* __restrict__ eraw, int E,
                           int* __restrict__ bcnt, int* __restrict__ bins) {
    int i = blockIdx.x * blockDim.x + threadIdx.x;
    if (i >= E) return;
    int s, d;
    if (g_is64) {
        const long long* e = (const long long*)eraw;
        s = (int)e[i];
        d = (int)e[(long long)E + i];
    } else {
        const int* e = (const int*)eraw;
        s = e[i];
        d = e[E + i];
    }
    int slot = atomicAdd(&bcnt[d], 1);
    if (slot < MAXDEG) {
        bins[d * MAXDEG + slot] = s;
    } else {
        int o = atomicAdd(&g_ovf_n, 1);
        if (o < OVF_CAP) g_ovf[o] = make_int2(s, d);
    }
}

// ---------------- gather-mean: one warp per dst row ---------------------------
__global__ void __launch_bounds__(256)
gather_kernel(const float* __restrict__ h,
              const int* __restrict__ bcnt,
              const int* __restrict__ bins,
              float* __restrict__ mean, int M) {
    int gw   = (blockIdx.x * blockDim.x + threadIdx.x) >> 5;
    int lane = threadIdx.x & 31;
    if (gw >= M) return;

    int deg = bcnt[gw];
    int nb  = min(deg, MAXDEG);

    int src0 = 0, src1 = 0;
    if (lane < nb)      src0 = bins[gw * MAXDEG + lane];
    if (lane + 32 < nb) src1 = bins[gw * MAXDEG + lane + 32];

    float4 acc0 = make_float4(0.f, 0.f, 0.f, 0.f);
    float4 acc1 = make_float4(0.f, 0.f, 0.f, 0.f);

    for (int i = 0; i < nb; i++) {
        int s = (i < 32) ? __shfl_sync(0xffffffffu, src0, i)
                         : __shfl_sync(0xffffffffu, src1, i - 32);
        const float4* row = (const float4*)(h + (size_t)s * D);
        float4 a = row[lane];
        float4 b = row[lane + 32];
        acc0.x += a.x; acc0.y += a.y; acc0.z += a.z; acc0.w += a.w;
        acc1.x += b.x; acc1.y += b.y; acc1.z += b.z; acc1.w += b.w;
    }

    float r = 1.0f / fmaxf((float)deg, 1.0f);
    float4* out = (float4*)(mean + (size_t)gw * D);
    acc0.x *= r; acc0.y *= r; acc0.z *= r; acc0.w *= r;
    acc1.x *= r; acc1.y *= r; acc1.z *= r; acc1.w *= r;
    out[lane]      = acc0;
    out[lane + 32] = acc1;
}

// ---------------- overflow fixup (expected no-op) ------------------------------
__device__ __forceinline__ void red_add_v4(float* p, float4 v) {
    asm volatile("red.global.add.v4.f32 [%0], {%1,%2,%3,%4};"
                 :: "l"(p), "f"(v.x), "f"(v.y), "f"(v.z), "f"(v.w)
                 : "memory");
}

__global__ void ovf_fix_kernel(const float* __restrict__ h,
                               const int* __restrict__ bcnt,
                               float* __restrict__ mean) {
    int n = g_ovf_n;
    if (n == 0) return;
    if (n > OVF_CAP) n = OVF_CAP;
    int lane = threadIdx.x & 31;
    int wid  = (blockIdx.x * blockDim.x + threadIdx.x) >> 5;
    int nw   = (gridDim.x * blockDim.x) >> 5;
    for (int k = wid; k < n; k += nw) {
        int2 sd = g_ovf[k];
        float r = 1.0f / fmaxf((float)bcnt[sd.y], 1.0f);
        const float4* row = (const float4*)(h + (size_t)sd.x * D);
        float* dst = mean + (size_t)sd.y * D;
#pragma unroll
        for (int j = 0; j < 2; j++) {
            int idx = lane + 32 * j;
            float4 v = row[idx];
            v.x *= r; v.y *= r; v.z *= r; v.w *= r;
            red_add_v4(dst + idx * 4, v);
        }
    }
}

// ---------------- fused SAGE GEMM (TF32 tensor cores, R2 layout) --------------
// C[m,:] = mean[m] @ Wl + h_dst[m] @ Wr + b   (optional ReLU)

#define AS_STRIDE 20
#define BS_STRIDE 136

__device__ __forceinline__ unsigned f2tf(float f) {
    unsigned u;
    asm("cvt.rna.tf32.f32 %0, %1;" : "=r"(u) : "f"(f));
    return u;
}
__device__ __forceinline__ unsigned fu(float f) { return __float_as_uint(f); }

__device__ __forceinline__ void mma_tf32(float c[4], const unsigned a[4],
                                         unsigned b0, unsigned b1) {
    asm volatile(
        "mma.sync.aligned.m16n8k8.row.col.f32.tf32.tf32.f32 "
        "{%0,%1,%2,%3}, {%4,%5,%6,%7}, {%8,%9}, {%0,%1,%2,%3};"
        : "+f"(c[0]), "+f"(c[1]), "+f"(c[2]), "+f"(c[3])
        : "r"(a[0]), "r"(a[1]), "r"(a[2]), "r"(a[3]), "r"(b0), "r"(b1));
}

__global__ void __launch_bounds__(256)
sage_gemm_tc(const float* __restrict__ A1,   // [M, 256] mean
             const float* __restrict__ A2,   // [M, 256] h_dst
             const float* __restrict__ Wl,
             const float* __restrict__ Wr,
             const float* __restrict__ bias,
             float* __restrict__ C,
             int M, int do_relu) {
    __shared__ float As[128 * AS_STRIDE];
    __shared__ float Bs[16 * BS_STRIDE];

    const int tid  = threadIdx.x;
    const int lane = tid & 31;
    const int warp = tid >> 5;
    const int wm   = warp >> 1;
    const int wn   = warp & 1;
    const int row0 = blockIdx.y * 128;
    const int col0 = blockIdx.x * 128;

    const int arow_l = tid >> 1;
    const int akslot = (tid & 1) * 8;
    const int brow_l = tid >> 4;
    const int bcol_l = (tid & 15) * 8;

    const int garow = row0 + arow_l;

    float acc[2][8][4];
#pragma unroll
    for (int mi = 0; mi < 2; mi++)
#pragma unroll
        for (int ni = 0; ni < 8; ni++)
#pragma unroll
            for (int j = 0; j < 4; j++) acc[mi][ni][j] = 0.0f;

    const int lr = lane >> 2;
    const int lc = lane & 3;

#pragma unroll
    for (int phase = 0; phase < 2; phase++) {
        const float* A = phase ? A2 : A1;
        const float* B = phase ? Wr : Wl;

        for (int k0 = 0; k0 < D; k0 += 16) {
#pragma unroll
            for (int h = 0; h < 2; h++) {
                float4 v = make_float4(0.f, 0.f, 0.f, 0.f);
                if (garow < M)
                    v = *(const float4*)(A + (size_t)garow * D + k0 + akslot + h * 4);
                float* p = &As[arow_l * AS_STRIDE + akslot + h * 4];
                p[0] = __uint_as_float(f2tf(v.x));
                p[1] = __uint_as_float(f2tf(v.y));
                p[2] = __uint_as_float(f2tf(v.z));
                p[3] = __uint_as_float(f2tf(v.w));
            }
#pragma unroll
            for (int h = 0; h < 2; h++) {
                float4 w = *(const float4*)(B + (size_t)(k0 + brow_l) * D + col0 + bcol_l + h * 4);
                float* p = &Bs[brow_l * BS_STRIDE + bcol_l + h * 4];
                p[0] = __uint_as_float(f2tf(w.x));
                p[1] = __uint_as_float(f2tf(w.y));
                p[2] = __uint_as_float(f2tf(w.z));
                p[3] = __uint_as_float(f2tf(w.w));
            }
            __syncthreads();

#pragma unroll
            for (int ks = 0; ks < 2; ks++) {
                const int k8 = ks * 8;
                unsigned a[2][4];
#pragma unroll
                for (int mi = 0; mi < 2; mi++) {
                    const int rb = wm * 32 + mi * 16 + lr;
                    a[mi][0] = fu(As[rb * AS_STRIDE + k8 + lc]);
                    a[mi][1] = fu(As[(rb + 8) * AS_STRIDE + k8 + lc]);
                    a[mi][2] = fu(As[rb * AS_STRIDE + k8 + lc + 4]);
                    a[mi][3] = fu(As[(rb + 8) * AS_STRIDE + k8 + lc + 4]);
                }
#pragma unroll
                for (int ni = 0; ni < 8; ni++) {
                    const int nb = wn * 64 + ni * 8 + lr;
                    unsigned b0 = fu(Bs[(k8 + lc) * BS_STRIDE + nb]);
                    unsigned b1 = fu(Bs[(k8 + lc + 4) * BS_STRIDE + nb]);
                    mma_tf32(acc[0][ni], a[0], b0, b1);
                    mma_tf32(acc[1][ni], a[1], b0, b1);
                }
            }
            __syncthreads();
        }
    }

#pragma unroll
    for (int mi = 0; mi < 2; mi++) {
        const int r = row0 + wm * 32 + mi * 16 + lr;
#pragma unroll
        for (int ni = 0; ni < 8; ni++) {
            const int cidx = col0 + wn * 64 + ni * 8 + lc * 2;
            const float bb0 = bias[cidx];
            const float bb1 = bias[cidx + 1];
            float v0 = acc[mi][ni][0] + bb0;
            float v1 = acc[mi][ni][1] + bb1;
            float v2 = acc[mi][ni][2] + bb0;
            float v3 = acc[mi][ni][3] + bb1;
            if (do_relu) {
                v0 = fmaxf(v0, 0.f); v1 = fmaxf(v1, 0.f);
                v2 = fmaxf(v2, 0.f); v3 = fmaxf(v3, 0.f);
            }
            if (r < M) {
                C[(size_t)r * D + cidx]     = v0;
                C[(size_t)r * D + cidx + 1] = v1;
            }
            if (r + 8 < M) {
                C[(size_t)(r + 8) * D + cidx]     = v2;
                C[(size_t)(r + 8) * D + cidx + 1] = v3;
            }
        }
    }
}

// ---------------- launch -----------------------------------------------------
extern "C" void kernel_launch(void* const* d_in, const int* in_sizes, int n_in,
                              void* d_out, int out_size) {
    const float* x   = (const float*)d_in[0];
    const void*  e0  = d_in[1];
    const void*  e1  = d_in[2];
    const void*  e2  = d_in[3];
    const float* Wl0 = (const float*)d_in[4];
    const float* b0  = (const float*)d_in[5];
    const float* Wr0 = (const float*)d_in[6];
    const float* Wl1 = (const float*)d_in[7];
    const float* b1  = (const float*)d_in[8];
    const float* Wr1 = (const float*)d_in[9];
    const float* Wl2 = (const float*)d_in[10];
    const float* b2  = (const float*)d_in[11];
    const float* Wr2 = (const float*)d_in[12];
    float* out = (float*)d_out;

    float *mean, *h1, *h2;
    int *bcnt, *bins;
    cudaGetSymbolAddress((void**)&mean, g_mean);
    cudaGetSymbolAddress((void**)&h1,   g_h1);
    cudaGetSymbolAddress((void**)&h2,   g_h2);
    cudaGetSymbolAddress((void**)&bcnt, g_bcnt);
    cudaGetSymbolAddress((void**)&bins, g_bins);

    detect_kernel<<<1, 32>>>((const int*)e0);

    // ---- layer 0: x[N0] -> h1[N1]
    zcnt_kernel<<<(N1 + 255) / 256, 256>>>(bcnt, N1);
    bin_kernel<<<(E0 + 255) / 256, 256>>>(e0, E0, bcnt, bins);
    gather_kernel<<<(N1 * 32 + 255) / 256, 256>>>(x, bcnt, bins, mean, N1);
    ovf_fix_kernel<<<2, 256>>>(x, bcnt, mean);
    sage_gemm_tc<<<dim3(2, (N1 + 127) / 128), 256>>>(
        mean, x, Wl0, Wr0, b0, h1, N1, 1);

    // ---- layer 1: h1[N1] -> h2[N2]
    zcnt_kernel<<<(N2 + 255) / 256, 256>>>(bcnt, N2);
    bin_kernel<<<(E1 + 255) / 256, 256>>>(e1, E1, bcnt, bins);
    gather_kernel<<<(N2 * 32 + 255) / 256, 256>>>(h1, bcnt, bins, mean, N2);
    ovf_fix_kernel<<<2, 256>>>(h1, bcnt, mean);
    sage_gemm_tc<<<dim3(2, (N2 + 127) / 128), 256>>>(
        mean, h1, Wl1, Wr1, b1, h2, N2, 1);

    // ---- layer 2: h2[N2] -> out[N3] (no ReLU)
    zcnt_kernel<<<(N3 + 255) / 256, 256>>>(bcnt, N3);
    bin_kernel<<<(E2 + 255) / 256, 256>>>(e2, E2, bcnt, bins);
    gather_kernel<<<(N3 * 32 + 255) / 256, 256>>>(h2, bcnt, bins, mean, N3);
    ovf_fix_kernel<<<2, 256>>>(h2, bcnt, mean);
    sage_gemm_tc<<<dim3(2, (N3 + 127) / 128), 256>>>(
        mean, h2, Wl2, Wr2, b2, out, N3, 0);
}